// round 6
// baseline (speedup 1.0000x reference)
#include <cuda_runtime.h>
#include <cuda_bf16.h>
#include <math.h>

// Problem constants (fixed for this problem instance)
#define NHd 8
#define NPt 4
#define HDm 32
static constexpr int Bb  = 4;
static constexpr int NQ  = 8192;
static constexpr int Cc  = 256;
static constexpr int Hh  = 128;
static constexpr int Ww  = 128;
static constexpr int HWp = Hh * Ww;
static constexpr int NQP = 96;   // packed small-GEMM width: 64 (off) + 32 (attn)

// Scratch (device globals — no allocation allowed)
__device__ float g_vp  [Bb * HWp * Cc];      // projected values, [B, H*W, C]
__device__ float g_qp  [Bb * NQ * NQP];      // packed off(0:64) | attn(64:96) per row
__device__ float g_mid [Bb * NQ * Cc];       // aggregated samples, [B, Nq, C]
__device__ float g_Wqp [Cc * NQP];           // packed weights  [256 x 96]
__device__ float g_bqp [NQP];                // packed bias     [96]

// ---------------------------------------------------------------------------
// Pack W_off [256x64] | W_attn [256x32] -> g_Wqp [256x96]; biases likewise.
// ---------------------------------------------------------------------------
__global__ void pack_qweights_kernel(
    const float* __restrict__ W_off, const float* __restrict__ b_off,
    const float* __restrict__ W_attn, const float* __restrict__ b_attn)
{
    const int i = blockIdx.x * blockDim.x + threadIdx.x;  // 0 .. 256*96-1
    if (i < Cc * NQP) {
        const int r = i / NQP, c = i % NQP;
        g_Wqp[i] = (c < 64) ? __ldg(W_off + r * 64 + c)
                            : __ldg(W_attn + r * 32 + (c - 64));
    }
    if (i < NQP)
        g_bqp[i] = (i < 64) ? __ldg(b_off + i) : __ldg(b_attn + (i - 64));
}

// ---------------------------------------------------------------------------
// Big SGEMM:  C[M,N] = A[M,K] @ B[K,N] + bias[N]
// Requirements: M % 128 == 0, N % 128 == 0, K % 16 == 0 (no guards).
// 128x128 block tile, BK=16, 256 threads, 8x8 per-thread (4+4 split rows/cols).
// FFMA:LDS cycle ratio 2:1 -> FMA-pipe bound.
// ---------------------------------------------------------------------------
__global__ __launch_bounds__(256, 2) void sgemm128_bias_kernel(
    const float* __restrict__ A, const float* __restrict__ Bm,
    const float* __restrict__ bias, float* __restrict__ Cout,
    int M, int N, int K)
{
    __shared__ float As[16][128];   // [k][m] (transposed A tile)
    __shared__ float Bs[16][128];   // [k][n]

    const int bm = blockIdx.x * 128;
    const int bn = blockIdx.y * 128;
    const int tid = threadIdx.x;
    const int tx = tid & 15;        // col group
    const int ty = tid >> 4;        // row group

    float acc[8][8] = {};
    float af[8], bf[8];

    for (int k0 = 0; k0 < K; k0 += 16) {
        // A tile: 128 rows x 16 k = 512 float4 (along k); 2 per thread.
        #pragma unroll
        for (int i = 0; i < 2; ++i) {
            const int v   = tid + i * 256;
            const int row = v >> 2;
            const int kk  = (v & 3) * 4;
            float4 a = __ldg(reinterpret_cast<const float4*>(
                A + (long)(bm + row) * K + k0 + kk));
            As[kk + 0][row] = a.x;
            As[kk + 1][row] = a.y;
            As[kk + 2][row] = a.z;
            As[kk + 3][row] = a.w;
        }
        // B tile: 16 k x 128 n = 512 float4 (along n); 2 per thread.
        #pragma unroll
        for (int i = 0; i < 2; ++i) {
            const int v   = tid + i * 256;
            const int kk  = v >> 5;
            const int col = (v & 31) * 4;
            float4 b = __ldg(reinterpret_cast<const float4*>(
                Bm + (long)(k0 + kk) * N + bn + col));
            *reinterpret_cast<float4*>(&Bs[kk][col]) = b;
        }
        __syncthreads();

        #pragma unroll
        for (int k = 0; k < 16; ++k) {
            *reinterpret_cast<float4*>(af)     = *reinterpret_cast<const float4*>(&As[k][ty * 4]);
            *reinterpret_cast<float4*>(af + 4) = *reinterpret_cast<const float4*>(&As[k][ty * 4 + 64]);
            *reinterpret_cast<float4*>(bf)     = *reinterpret_cast<const float4*>(&Bs[k][tx * 4]);
            *reinterpret_cast<float4*>(bf + 4) = *reinterpret_cast<const float4*>(&Bs[k][tx * 4 + 64]);
            #pragma unroll
            for (int i = 0; i < 8; ++i)
                #pragma unroll
                for (int j = 0; j < 8; ++j)
                    acc[i][j] = fmaf(af[i], bf[j], acc[i][j]);
        }
        __syncthreads();
    }

    // Epilogue: rows ty*4+{0..3} and +64; cols tx*4+{0..3} and +64. float4 stores.
    float4 bia0 = __ldg(reinterpret_cast<const float4*>(bias + bn + tx * 4));
    float4 bia1 = __ldg(reinterpret_cast<const float4*>(bias + bn + tx * 4 + 64));
    #pragma unroll
    for (int i = 0; i < 8; ++i) {
        const int row = bm + ty * 4 + (i & 3) + (i >> 2) * 64;
        float4 c0, c1;
        c0.x = acc[i][0] + bia0.x; c0.y = acc[i][1] + bia0.y;
        c0.z = acc[i][2] + bia0.z; c0.w = acc[i][3] + bia0.w;
        c1.x = acc[i][4] + bia1.x; c1.y = acc[i][5] + bia1.y;
        c1.z = acc[i][6] + bia1.z; c1.w = acc[i][7] + bia1.w;
        *reinterpret_cast<float4*>(Cout + (long)row * N + bn + tx * 4)      = c0;
        *reinterpret_cast<float4*>(Cout + (long)row * N + bn + tx * 4 + 64) = c1;
    }
}

// ---------------------------------------------------------------------------
// Small-N SGEMM:  C[M,N] = A[M,K] @ B[K,N] + bias[N]
// Requirements: M % 64 == 0, K % 16 == 0.  N arbitrary (column-guarded).
// 64x64 block tile, BK=16, 256 threads, 4x4 per-thread register tile.
// ---------------------------------------------------------------------------
__global__ __launch_bounds__(256) void sgemm_bias_kernel(
    const float* __restrict__ A, const float* __restrict__ Bm,
    const float* __restrict__ bias, float* __restrict__ Cout,
    int M, int N, int K)
{
    __shared__ float As[16][64];   // [k][m]
    __shared__ float Bs[16][64];   // [k][n]

    const int bm = blockIdx.x * 64;
    const int bn = blockIdx.y * 64;
    const int tid = threadIdx.x;
    const int tx = tid & 15;
    const int ty = tid >> 4;

    const int arow = tid >> 2;
    const int ak   = (tid & 3) * 4;
    const int bk   = tid >> 4;
    const int bcol = (tid & 15) * 4;

    float acc[4][4] = {};

    for (int k0 = 0; k0 < K; k0 += 16) {
        float4 a = __ldg(reinterpret_cast<const float4*>(
            A + (long)(bm + arow) * K + k0 + ak));
        As[ak + 0][arow] = a.x;
        As[ak + 1][arow] = a.y;
        As[ak + 2][arow] = a.z;
        As[ak + 3][arow] = a.w;

        const int gk = k0 + bk;
        const int gc = bn + bcol;
        float4 bv;
        bv.x = (gc + 0 < N) ? __ldg(Bm + (long)gk * N + gc + 0) : 0.0f;
        bv.y = (gc + 1 < N) ? __ldg(Bm + (long)gk * N + gc + 1) : 0.0f;
        bv.z = (gc + 2 < N) ? __ldg(Bm + (long)gk * N + gc + 2) : 0.0f;
        bv.w = (gc + 3 < N) ? __ldg(Bm + (long)gk * N + gc + 3) : 0.0f;
        *reinterpret_cast<float4*>(&Bs[bk][bcol]) = bv;

        __syncthreads();

        #pragma unroll
        for (int k = 0; k < 16; ++k) {
            float4 av = *reinterpret_cast<const float4*>(&As[k][ty * 4]);
            float4 bb = *reinterpret_cast<const float4*>(&Bs[k][tx * 4]);
            acc[0][0] += av.x * bb.x; acc[0][1] += av.x * bb.y;
            acc[0][2] += av.x * bb.z; acc[0][3] += av.x * bb.w;
            acc[1][0] += av.y * bb.x; acc[1][1] += av.y * bb.y;
            acc[1][2] += av.y * bb.z; acc[1][3] += av.y * bb.w;
            acc[2][0] += av.z * bb.x; acc[2][1] += av.z * bb.y;
            acc[2][2] += av.z * bb.z; acc[2][3] += av.z * bb.w;
            acc[3][0] += av.w * bb.x; acc[3][1] += av.w * bb.y;
            acc[3][2] += av.w * bb.z; acc[3][3] += av.w * bb.w;
        }
        __syncthreads();
    }

    #pragma unroll
    for (int i = 0; i < 4; ++i) {
        const int row = bm + ty * 4 + i;
        #pragma unroll
        for (int j = 0; j < 4; ++j) {
            const int col = bn + tx * 4 + j;
            if (col < N)
                Cout[(long)row * N + col] = acc[i][j] + __ldg(bias + col);
        }
    }
}

// ---------------------------------------------------------------------------
// Deformable sampling: one block per (b, q); one warp per head; lane = channel.
// Reads packed g_qp (off | attn logits) and g_vp; writes g_mid.
// Each corner gather is one coalesced 128B line (32 lanes x fp32).
// ---------------------------------------------------------------------------
__global__ __launch_bounds__(NHd * 32) void deform_sample_kernel(
    const float* __restrict__ ref)
{
    const int row  = blockIdx.x;          // b*NQ + q
    const int b    = row / NQ;
    const int h    = threadIdx.x >> 5;    // head
    const int lane = threadIdx.x & 31;    // channel within head

    const float rx = __ldg(ref + (long)row * 2 + 0);
    const float ry = __ldg(ref + (long)row * 2 + 1);

    const float* qrow = g_qp + (long)row * NQP;
    const float* offp = qrow + h * (NPt * 2);       // offsets at [0,64)
    const float* logp = qrow + 64 + h * NPt;        // attn logits at [64,96)

    // softmax over NP=4 (all lanes redundantly; trivial cost)
    float l0 = logp[0], l1 = logp[1], l2 = logp[2], l3 = logp[3];
    float mx = fmaxf(fmaxf(l0, l1), fmaxf(l2, l3));
    float e[4];
    e[0] = expf(l0 - mx); e[1] = expf(l1 - mx);
    e[2] = expf(l2 - mx); e[3] = expf(l3 - mx);
    const float inv = 1.0f / (e[0] + e[1] + e[2] + e[3]);

    const float* vb = g_vp + (long)b * HWp * Cc + h * HDm + lane;

    float acc = 0.0f;
    #pragma unroll
    for (int p = 0; p < NPt; ++p) {
        const float ox = offp[p * 2 + 0] * (0.1f / (float)Ww);
        const float oy = offp[p * 2 + 1] * (0.1f / (float)Hh);
        const float lx = fminf(fmaxf(rx + ox, 0.0f), 1.0f);
        const float ly = fminf(fmaxf(ry + oy, 0.0f), 1.0f);
        const float gx = fminf(fmaxf(lx * (float)Ww - 0.5f, 0.0f), (float)(Ww - 1));
        const float gy = fminf(fmaxf(ly * (float)Hh - 0.5f, 0.0f), (float)(Hh - 1));
        const float x0f = floorf(gx), y0f = floorf(gy);
        const float fx = gx - x0f, fy = gy - y0f;
        const int x0 = (int)x0f, y0 = (int)y0f;
        const int x1 = min(x0 + 1, Ww - 1);
        const int y1 = min(y0 + 1, Hh - 1);

        const float aw = e[p] * inv;

        const float* r0 = vb + (long)(y0 * Ww) * Cc;
        const float* r1 = vb + (long)(y1 * Ww) * Cc;
        const float v00 = __ldg(r0 + (long)x0 * Cc);
        const float v10 = __ldg(r0 + (long)x1 * Cc);
        const float v01 = __ldg(r1 + (long)x0 * Cc);
        const float v11 = __ldg(r1 + (long)x1 * Cc);

        const float top = v00 + fx * (v10 - v00);
        const float bot = v01 + fx * (v11 - v01);
        acc = fmaf(aw, top + fy * (bot - top), acc);
    }

    g_mid[(long)row * Cc + h * HDm + lane] = acc;
}

// ---------------------------------------------------------------------------
extern "C" void kernel_launch(void* const* d_in, const int* in_sizes, int n_in,
                              void* d_out, int out_size)
{
    const float* query  = (const float*)d_in[0];
    const float* refp   = (const float*)d_in[1];
    const float* value  = (const float*)d_in[2];
    const float* W_off  = (const float*)d_in[3];
    const float* b_off  = (const float*)d_in[4];
    const float* W_attn = (const float*)d_in[5];
    const float* b_attn = (const float*)d_in[6];
    const float* W_val  = (const float*)d_in[7];
    const float* b_val  = (const float*)d_in[8];
    const float* W_out  = (const float*)d_in[9];
    const float* b_out  = (const float*)d_in[10];
    float* out = (float*)d_out;

    // Resolve scratch symbol addresses once (host-side lookup, capture-safe).
    static float *vp = nullptr, *qp = nullptr, *mid = nullptr, *Wqp = nullptr, *bqp = nullptr;
    if (!vp) {
        cudaGetSymbolAddress((void**)&vp,  g_vp);
        cudaGetSymbolAddress((void**)&qp,  g_qp);
        cudaGetSymbolAddress((void**)&mid, g_mid);
        cudaGetSymbolAddress((void**)&Wqp, g_Wqp);
        cudaGetSymbolAddress((void**)&bqp, g_bqp);
    }

    const int Mq = Bb * NQ;     // 32768
    const int Mv = Bb * HWp;    // 65536

    // 0) pack query-projection weights (trivial)
    pack_qweights_kernel<<<(Cc * NQP + 255) / 256, 256>>>(W_off, b_off, W_attn, b_attn);

    // 1) value projection: vp = value @ W_val + b_val     [65536 x 256]
    {
        dim3 grid(Mv / 128, Cc / 128);
        sgemm128_bias_kernel<<<grid, 256>>>(value, W_val, b_val, vp, Mv, Cc, Cc);
    }
    // 2) fused query projections: qp = query @ [W_off|W_attn] + b   [32768 x 96]
    {
        dim3 grid(Mq / 64, (NQP + 63) / 64);
        sgemm_bias_kernel<<<grid, 256>>>(query, Wqp, bqp, qp, Mq, NQP, Cc);
    }
    // 3) softmax + bilinear sampling + head aggregation -> mid
    {
        deform_sample_kernel<<<Mq, NHd * 32>>>(refp);
    }
    // 4) output projection: out = mid @ W_out + b_out     [32768 x 256]
    {
        dim3 grid(Mq / 128, Cc / 128);
        sgemm128_bias_kernel<<<grid, 256>>>(mid, W_out, b_out, out, Mq, Cc, Cc);
    }
}

// round 8
// speedup vs baseline: 1.7252x; 1.7252x over previous
#include <cuda_runtime.h>
#include <cuda_bf16.h>
#include <math.h>

// Problem constants (fixed for this problem instance)
#define NHd 8
#define NPt 4
#define HDm 32
static constexpr int Bb  = 4;
static constexpr int NQ  = 8192;
static constexpr int Cc  = 256;
static constexpr int Hh  = 128;
static constexpr int Ww  = 128;
static constexpr int HWp = Hh * Ww;
static constexpr int NQP = 96;   // packed small-GEMM width: 64 (off) + 32 (attn)

// Scratch (device globals — no allocation allowed)
__device__ float g_vp  [Bb * HWp * Cc];      // projected values, [B, H*W, C]
__device__ float g_qp  [Bb * NQ * NQP];      // packed off(0:64) | attn(64:96) per row
__device__ float g_mid [Bb * NQ * Cc];       // aggregated samples, [B, Nq, C]
__device__ float g_Wqp [Cc * NQP];           // packed weights  [256 x 96]
__device__ float g_bqp [NQP];                // packed bias     [96]

// ---------------------------------------------------------------------------
// Pack W_off [256x64] | W_attn [256x32] -> g_Wqp [256x96]; biases likewise.
// ---------------------------------------------------------------------------
__global__ void pack_qweights_kernel(
    const float* __restrict__ W_off, const float* __restrict__ b_off,
    const float* __restrict__ W_attn, const float* __restrict__ b_attn)
{
    const int i = blockIdx.x * blockDim.x + threadIdx.x;  // 0 .. 256*96-1
    if (i < Cc * NQP) {
        const int r = i / NQP, c = i % NQP;
        g_Wqp[i] = (c < 64) ? __ldg(W_off + r * 64 + c)
                            : __ldg(W_attn + r * 32 + (c - 64));
    }
    if (i < NQP)
        g_bqp[i] = (i < 64) ? __ldg(b_off + i) : __ldg(b_attn + (i - 64));
}

// ---------------------------------------------------------------------------
// tf32 tensor-core GEMM:  C[M,N] = A[M,K] @ B[K,N] + bias[N]
// Requirements: M % 128 == 0, N % 128 == 0, K % 32 == 0.
// 128x128 CTA tile, BK=32, 256 threads (8 warps as 2m x 4n, warp tile 64x32).
// mma.sync.m16n8k8.tf32, fp32 accum. cp.async double-buffered smem.
// Smem layouts (padded, fragment-load conflict-free):
//   A_s[128][36]  (bank = 4m+k, distinct over warp)
//   B_s[32][136]  (bank = 8k+n, distinct over warp)
// ---------------------------------------------------------------------------
static constexpr int TF_AS = 128 * 36;          // floats per A stage
static constexpr int TF_BS = 32 * 136;          // floats per B stage
static constexpr int TF_STAGE = TF_AS + TF_BS;  // 8960 floats = 35840 B
static constexpr int TF_SMEM_BYTES = 2 * TF_STAGE * 4;  // 71680 B

__device__ __forceinline__ unsigned f2tf32(float f) {
    unsigned r;
    asm("cvt.rna.tf32.f32 %0, %1;" : "=r"(r) : "f"(f));
    return r;
}

__device__ __forceinline__ void mma_tf32(float* c, const unsigned* a, const unsigned* b) {
    asm volatile(
        "mma.sync.aligned.m16n8k8.row.col.f32.tf32.tf32.f32 "
        "{%0,%1,%2,%3},{%4,%5,%6,%7},{%8,%9},{%0,%1,%2,%3};"
        : "+f"(c[0]), "+f"(c[1]), "+f"(c[2]), "+f"(c[3])
        : "r"(a[0]), "r"(a[1]), "r"(a[2]), "r"(a[3]), "r"(b[0]), "r"(b[1]));
}

__device__ __forceinline__ void cp_async16(unsigned smem_addr, const void* gptr) {
    asm volatile("cp.async.ca.shared.global [%0], [%1], 16;"
                 :: "r"(smem_addr), "l"(gptr));
}

__global__ __launch_bounds__(256, 2) void sgemm_tf32_bias_kernel(
    const float* __restrict__ A, const float* __restrict__ Bm,
    const float* __restrict__ bias, float* __restrict__ Cout,
    int M, int N, int K)
{
    extern __shared__ float sm[];
    const unsigned smbase = (unsigned)__cvta_generic_to_shared(sm);

    const int tid  = threadIdx.x;
    const int wid  = tid >> 5, lane = tid & 31;
    const int grp  = lane >> 2, tig = lane & 3;
    const int warp_m = wid >> 2;          // 0..1 -> m offset *64
    const int warp_n = wid & 3;           // 0..3 -> n offset *32
    const int bm = blockIdx.x * 128;
    const int bn = blockIdx.y * 128;

    float c[4][4][4] = {};                // [mi][ni][reg]

    // cp.async tile loaders (4 float4 per thread each for A and B)
    auto load_tiles = [&](int s, int k0) {
        const unsigned abase = smbase + (unsigned)(s * TF_STAGE) * 4u;
        const unsigned bbase = abase + (unsigned)TF_AS * 4u;
        #pragma unroll
        for (int i = 0; i < 4; ++i) {
            const int v   = tid + i * 256;       // 0..1023
            const int row = v >> 3;              // 0..127
            const int kq  = v & 7;               // float4 within 32-k row
            cp_async16(abase + (unsigned)(row * 36 + kq * 4) * 4u,
                       A + (long)(bm + row) * K + k0 + kq * 4);
        }
        #pragma unroll
        for (int i = 0; i < 4; ++i) {
            const int v    = tid + i * 256;
            const int krow = v >> 5;             // 0..31
            const int n4   = v & 31;             // float4 within 128-n row
            cp_async16(bbase + (unsigned)(krow * 136 + n4 * 4) * 4u,
                       Bm + (long)(k0 + krow) * N + bn + n4 * 4);
        }
        asm volatile("cp.async.commit_group;");
    };

    const int nIters = K / 32;
    load_tiles(0, 0);

    for (int it = 0; it < nIters; ++it) {
        const int s = it & 1;
        if (it + 1 < nIters) {
            load_tiles(s ^ 1, (it + 1) * 32);
            asm volatile("cp.async.wait_group 1;");
        } else {
            asm volatile("cp.async.wait_group 0;");
        }
        __syncthreads();

        const float* As_ = sm + s * TF_STAGE;
        const float* Bs_ = As_ + TF_AS;

        #pragma unroll
        for (int ks = 0; ks < 4; ++ks) {
            const int kk = ks * 8;
            unsigned a[4][4], b[4][2];
            #pragma unroll
            for (int mi = 0; mi < 4; ++mi) {
                const int m = warp_m * 64 + mi * 16 + grp;
                a[mi][0] = f2tf32(As_[m       * 36 + kk + tig]);
                a[mi][1] = f2tf32(As_[(m + 8) * 36 + kk + tig]);
                a[mi][2] = f2tf32(As_[m       * 36 + kk + tig + 4]);
                a[mi][3] = f2tf32(As_[(m + 8) * 36 + kk + tig + 4]);
            }
            #pragma unroll
            for (int ni = 0; ni < 4; ++ni) {
                const int n = warp_n * 32 + ni * 8 + grp;
                b[ni][0] = f2tf32(Bs_[(kk + tig)     * 136 + n]);
                b[ni][1] = f2tf32(Bs_[(kk + tig + 4) * 136 + n]);
            }
            #pragma unroll
            for (int mi = 0; mi < 4; ++mi)
                #pragma unroll
                for (int ni = 0; ni < 4; ++ni)
                    mma_tf32(c[mi][ni], a[mi], b[ni]);
        }
        __syncthreads();
    }

    // Epilogue: c0/c1 -> (row, 2*tig / +1); c2/c3 -> row+8. float2 stores.
    #pragma unroll
    for (int ni = 0; ni < 4; ++ni) {
        const int col = bn + warp_n * 32 + ni * 8 + 2 * tig;
        const float bx = __ldg(bias + col);
        const float by = __ldg(bias + col + 1);
        #pragma unroll
        for (int mi = 0; mi < 4; ++mi) {
            const int row0 = bm + warp_m * 64 + mi * 16 + grp;
            float2 v0, v1;
            v0.x = c[mi][ni][0] + bx; v0.y = c[mi][ni][1] + by;
            v1.x = c[mi][ni][2] + bx; v1.y = c[mi][ni][3] + by;
            *reinterpret_cast<float2*>(Cout + (long)row0 * N + col)       = v0;
            *reinterpret_cast<float2*>(Cout + (long)(row0 + 8) * N + col) = v1;
        }
    }
}

// ---------------------------------------------------------------------------
// Small-N SGEMM (FFMA):  C[M,N] = A[M,K] @ B[K,N] + bias[N]
// M % 64 == 0, K % 16 == 0, N arbitrary (column-guarded). 64x64 tile.
// ---------------------------------------------------------------------------
__global__ __launch_bounds__(256) void sgemm_bias_kernel(
    const float* __restrict__ A, const float* __restrict__ Bm,
    const float* __restrict__ bias, float* __restrict__ Cout,
    int M, int N, int K)
{
    __shared__ float As[16][64];   // [k][m]
    __shared__ float Bs[16][64];   // [k][n]

    const int bm = blockIdx.x * 64;
    const int bn = blockIdx.y * 64;
    const int tid = threadIdx.x;
    const int tx = tid & 15;
    const int ty = tid >> 4;

    const int arow = tid >> 2;
    const int ak   = (tid & 3) * 4;
    const int bk   = tid >> 4;
    const int bcol = (tid & 15) * 4;

    float acc[4][4] = {};

    for (int k0 = 0; k0 < K; k0 += 16) {
        float4 a = __ldg(reinterpret_cast<const float4*>(
            A + (long)(bm + arow) * K + k0 + ak));
        As[ak + 0][arow] = a.x;
        As[ak + 1][arow] = a.y;
        As[ak + 2][arow] = a.z;
        As[ak + 3][arow] = a.w;

        const int gk = k0 + bk;
        const int gc = bn + bcol;
        float4 bv;
        bv.x = (gc + 0 < N) ? __ldg(Bm + (long)gk * N + gc + 0) : 0.0f;
        bv.y = (gc + 1 < N) ? __ldg(Bm + (long)gk * N + gc + 1) : 0.0f;
        bv.z = (gc + 2 < N) ? __ldg(Bm + (long)gk * N + gc + 2) : 0.0f;
        bv.w = (gc + 3 < N) ? __ldg(Bm + (long)gk * N + gc + 3) : 0.0f;
        *reinterpret_cast<float4*>(&Bs[bk][bcol]) = bv;

        __syncthreads();

        #pragma unroll
        for (int k = 0; k < 16; ++k) {
            float4 av = *reinterpret_cast<const float4*>(&As[k][ty * 4]);
            float4 bb = *reinterpret_cast<const float4*>(&Bs[k][tx * 4]);
            acc[0][0] += av.x * bb.x; acc[0][1] += av.x * bb.y;
            acc[0][2] += av.x * bb.z; acc[0][3] += av.x * bb.w;
            acc[1][0] += av.y * bb.x; acc[1][1] += av.y * bb.y;
            acc[1][2] += av.y * bb.z; acc[1][3] += av.y * bb.w;
            acc[2][0] += av.z * bb.x; acc[2][1] += av.z * bb.y;
            acc[2][2] += av.z * bb.z; acc[2][3] += av.z * bb.w;
            acc[3][0] += av.w * bb.x; acc[3][1] += av.w * bb.y;
            acc[3][2] += av.w * bb.z; acc[3][3] += av.w * bb.w;
        }
        __syncthreads();
    }

    #pragma unroll
    for (int i = 0; i < 4; ++i) {
        const int row = bm + ty * 4 + i;
        #pragma unroll
        for (int j = 0; j < 4; ++j) {
            const int col = bn + tx * 4 + j;
            if (col < N)
                Cout[(long)row * N + col] = acc[i][j] + __ldg(bias + col);
        }
    }
}

// ---------------------------------------------------------------------------
// Deformable sampling: one block per (b, q); one warp per head; lane = channel.
// Reads packed g_qp (off | attn logits) and g_vp; writes g_mid.
// Each corner gather is one coalesced 128B line (32 lanes x fp32).
// ---------------------------------------------------------------------------
__global__ __launch_bounds__(NHd * 32) void deform_sample_kernel(
    const float* __restrict__ ref)
{
    const int row  = blockIdx.x;          // b*NQ + q
    const int b    = row / NQ;
    const int h    = threadIdx.x >> 5;    // head
    const int lane = threadIdx.x & 31;    // channel within head

    const float rx = __ldg(ref + (long)row * 2 + 0);
    const float ry = __ldg(ref + (long)row * 2 + 1);

    const float* qrow = g_qp + (long)row * NQP;
    const float* offp = qrow + h * (NPt * 2);       // offsets at [0,64)
    const float* logp = qrow + 64 + h * NPt;        // attn logits at [64,96)

    // softmax over NP=4 (all lanes redundantly; trivial cost)
    float l0 = logp[0], l1 = logp[1], l2 = logp[2], l3 = logp[3];
    float mx = fmaxf(fmaxf(l0, l1), fmaxf(l2, l3));
    float e[4];
    e[0] = expf(l0 - mx); e[1] = expf(l1 - mx);
    e[2] = expf(l2 - mx); e[3] = expf(l3 - mx);
    const float inv = 1.0f / (e[0] + e[1] + e[2] + e[3]);

    const float* vb = g_vp + (long)b * HWp * Cc + h * HDm + lane;

    float acc = 0.0f;
    #pragma unroll
    for (int p = 0; p < NPt; ++p) {
        const float ox = offp[p * 2 + 0] * (0.1f / (float)Ww);
        const float oy = offp[p * 2 + 1] * (0.1f / (float)Hh);
        const float lx = fminf(fmaxf(rx + ox, 0.0f), 1.0f);
        const float ly = fminf(fmaxf(ry + oy, 0.0f), 1.0f);
        const float gx = fminf(fmaxf(lx * (float)Ww - 0.5f, 0.0f), (float)(Ww - 1));
        const float gy = fminf(fmaxf(ly * (float)Hh - 0.5f, 0.0f), (float)(Hh - 1));
        const float x0f = floorf(gx), y0f = floorf(gy);
        const float fx = gx - x0f, fy = gy - y0f;
        const int x0 = (int)x0f, y0 = (int)y0f;
        const int x1 = min(x0 + 1, Ww - 1);
        const int y1 = min(y0 + 1, Hh - 1);

        const float aw = e[p] * inv;

        const float* r0 = vb + (long)(y0 * Ww) * Cc;
        const float* r1 = vb + (long)(y1 * Ww) * Cc;
        const float v00 = __ldg(r0 + (long)x0 * Cc);
        const float v10 = __ldg(r0 + (long)x1 * Cc);
        const float v01 = __ldg(r1 + (long)x0 * Cc);
        const float v11 = __ldg(r1 + (long)x1 * Cc);

        const float top = v00 + fx * (v10 - v00);
        const float bot = v01 + fx * (v11 - v01);
        acc = fmaf(aw, top + fy * (bot - top), acc);
    }

    g_mid[(long)row * Cc + h * HDm + lane] = acc;
}

// ---------------------------------------------------------------------------
extern "C" void kernel_launch(void* const* d_in, const int* in_sizes, int n_in,
                              void* d_out, int out_size)
{
    const float* query  = (const float*)d_in[0];
    const float* refp   = (const float*)d_in[1];
    const float* value  = (const float*)d_in[2];
    const float* W_off  = (const float*)d_in[3];
    const float* b_off  = (const float*)d_in[4];
    const float* W_attn = (const float*)d_in[5];
    const float* b_attn = (const float*)d_in[6];
    const float* W_val  = (const float*)d_in[7];
    const float* b_val  = (const float*)d_in[8];
    const float* W_out  = (const float*)d_in[9];
    const float* b_out  = (const float*)d_in[10];
    float* out = (float*)d_out;

    // One-time host-side setup (capture-safe: no stream ops).
    static float *vp = nullptr, *qp = nullptr, *mid = nullptr, *Wqp = nullptr, *bqp = nullptr;
    if (!vp) {
        cudaGetSymbolAddress((void**)&vp,  g_vp);
        cudaGetSymbolAddress((void**)&qp,  g_qp);
        cudaGetSymbolAddress((void**)&mid, g_mid);
        cudaGetSymbolAddress((void**)&Wqp, g_Wqp);
        cudaGetSymbolAddress((void**)&bqp, g_bqp);
        cudaFuncSetAttribute(sgemm_tf32_bias_kernel,
                             cudaFuncAttributeMaxDynamicSharedMemorySize,
                             TF_SMEM_BYTES);
    }

    const int Mq = Bb * NQ;     // 32768
    const int Mv = Bb * HWp;    // 65536

    // 0) pack query-projection weights (trivial)
    pack_qweights_kernel<<<(Cc * NQP + 255) / 256, 256>>>(W_off, b_off, W_attn, b_attn);

    // 1) value projection (tf32 MMA): vp = value @ W_val + b_val   [65536 x 256]
    {
        dim3 grid(Mv / 128, Cc / 128);
        sgemm_tf32_bias_kernel<<<grid, 256, TF_SMEM_BYTES>>>(value, W_val, b_val, vp, Mv, Cc, Cc);
    }
    // 2) fused query projections (FFMA): qp = query @ [W_off|W_attn] + b   [32768 x 96]
    {
        dim3 grid(Mq / 64, (NQP + 63) / 64);
        sgemm_bias_kernel<<<grid, 256>>>(query, Wqp, bqp, qp, Mq, NQP, Cc);
    }
    // 3) softmax + bilinear sampling + head aggregation -> mid
    {
        deform_sample_kernel<<<Mq, NHd * 32>>>(refp);
    }
    // 4) output projection (tf32 MMA): out = mid @ W_out + b_out   [32768 x 256]
    {
        dim3 grid(Mq / 128, Cc / 128);
        sgemm_tf32_bias_kernel<<<grid, 256, TF_SMEM_BYTES>>>(mid, W_out, b_out, out, Mq, Cc, Cc);
    }
}

// round 12
// speedup vs baseline: 2.0138x; 1.1672x over previous
#include <cuda_runtime.h>
#include <cuda_bf16.h>
#include <math.h>

// Problem constants (fixed for this problem instance)
#define NHd 8
#define NPt 4
#define HDm 32
static constexpr int Bb  = 4;
static constexpr int NQ  = 8192;
static constexpr int Cc  = 256;
static constexpr int Hh  = 128;
static constexpr int Ww  = 128;
static constexpr int HWp = Hh * Ww;
static constexpr int NQP = 96;   // packed small-GEMM width: 64 (off) + 32 (attn)

// Scratch (device globals — no allocation allowed)
__device__ float g_vp  [Bb * HWp * Cc];      // projected values, [B, H*W, C]
__device__ float g_qp  [Bb * NQ * NQP];      // packed off(0:64) | attn(64:96) per row
__device__ float g_mid [Bb * NQ * Cc];       // aggregated samples, [B, Nq, C]
__device__ float g_Wqp [Cc * NQP];           // packed weights  [256 x 96]
__device__ float g_bqp [NQP];                // packed bias     [96]

// ---------------------------------------------------------------------------
// Pack W_off [256x64] | W_attn [256x32] -> g_Wqp [256x96]; biases likewise.
// ---------------------------------------------------------------------------
__global__ void pack_qweights_kernel(
    const float* __restrict__ W_off, const float* __restrict__ b_off,
    const float* __restrict__ W_attn, const float* __restrict__ b_attn)
{
    const int i = blockIdx.x * blockDim.x + threadIdx.x;  // 0 .. 256*96-1
    if (i < Cc * NQP) {
        const int r = i / NQP, c = i % NQP;
        g_Wqp[i] = (c < 64) ? __ldg(W_off + r * 64 + c)
                            : __ldg(W_attn + r * 32 + (c - 64));
    }
    if (i < NQP)
        g_bqp[i] = (i < 64) ? __ldg(b_off + i) : __ldg(b_attn + (i - 64));
}

// ---------------------------------------------------------------------------
// tf32 tensor-core GEMM:  C[M,N] = A[M,K] @ B[K,N] + bias[N]
// Requirements: M % 128 == 0, N % 128 == 0, K % 32 == 0.
// 128x128 CTA tile, BK=32, 256 threads (8 warps as 2m x 4n, warp tile 64x32).
// mma.sync.m16n8k8.tf32, fp32 accum. cp.async double-buffered smem.
// ---------------------------------------------------------------------------
static constexpr int TF_AS = 128 * 36;          // floats per A stage
static constexpr int TF_BS = 32 * 136;          // floats per B stage
static constexpr int TF_STAGE = TF_AS + TF_BS;  // 8960 floats = 35840 B
static constexpr int TF_SMEM_BYTES = 2 * TF_STAGE * 4;  // 71680 B

__device__ __forceinline__ unsigned f2tf32(float f) {
    unsigned r;
    asm("cvt.rna.tf32.f32 %0, %1;" : "=r"(r) : "f"(f));
    return r;
}

__device__ __forceinline__ void mma_tf32(float* c, const unsigned* a, const unsigned* b) {
    asm volatile(
        "mma.sync.aligned.m16n8k8.row.col.f32.tf32.tf32.f32 "
        "{%0,%1,%2,%3},{%4,%5,%6,%7},{%8,%9},{%0,%1,%2,%3};"
        : "+f"(c[0]), "+f"(c[1]), "+f"(c[2]), "+f"(c[3])
        : "r"(a[0]), "r"(a[1]), "r"(a[2]), "r"(a[3]), "r"(b[0]), "r"(b[1]));
}

__device__ __forceinline__ void cp_async16(unsigned smem_addr, const void* gptr) {
    asm volatile("cp.async.ca.shared.global [%0], [%1], 16;"
                 :: "r"(smem_addr), "l"(gptr));
}

__global__ __launch_bounds__(256, 2) void sgemm_tf32_bias_kernel(
    const float* __restrict__ A, const float* __restrict__ Bm,
    const float* __restrict__ bias, float* __restrict__ Cout,
    int M, int N, int K)
{
    extern __shared__ float sm[];
    const unsigned smbase = (unsigned)__cvta_generic_to_shared(sm);

    const int tid  = threadIdx.x;
    const int wid  = tid >> 5, lane = tid & 31;
    const int grp  = lane >> 2, tig = lane & 3;
    const int warp_m = wid >> 2;          // 0..1 -> m offset *64
    const int warp_n = wid & 3;           // 0..3 -> n offset *32
    const int bm = blockIdx.x * 128;
    const int bn = blockIdx.y * 128;

    float c[4][4][4] = {};                // [mi][ni][reg]

    auto load_tiles = [&](int s, int k0) {
        const unsigned abase = smbase + (unsigned)(s * TF_STAGE) * 4u;
        const unsigned bbase = abase + (unsigned)TF_AS * 4u;
        #pragma unroll
        for (int i = 0; i < 4; ++i) {
            const int v   = tid + i * 256;       // 0..1023
            const int row = v >> 3;              // 0..127
            const int kq  = v & 7;               // float4 within 32-k row
            cp_async16(abase + (unsigned)(row * 36 + kq * 4) * 4u,
                       A + (long)(bm + row) * K + k0 + kq * 4);
        }
        #pragma unroll
        for (int i = 0; i < 4; ++i) {
            const int v    = tid + i * 256;
            const int krow = v >> 5;             // 0..31
            const int n4   = v & 31;             // float4 within 128-n row
            cp_async16(bbase + (unsigned)(krow * 136 + n4 * 4) * 4u,
                       Bm + (long)(k0 + krow) * N + bn + n4 * 4);
        }
        asm volatile("cp.async.commit_group;");
    };

    const int nIters = K / 32;
    load_tiles(0, 0);

    for (int it = 0; it < nIters; ++it) {
        const int s = it & 1;
        if (it + 1 < nIters) {
            load_tiles(s ^ 1, (it + 1) * 32);
            asm volatile("cp.async.wait_group 1;");
        } else {
            asm volatile("cp.async.wait_group 0;");
        }
        __syncthreads();

        const float* As_ = sm + s * TF_STAGE;
        const float* Bs_ = As_ + TF_AS;

        #pragma unroll
        for (int ks = 0; ks < 4; ++ks) {
            const int kk = ks * 8;
            unsigned a[4][4], b[4][2];
            #pragma unroll
            for (int mi = 0; mi < 4; ++mi) {
                const int m = warp_m * 64 + mi * 16 + grp;
                a[mi][0] = f2tf32(As_[m       * 36 + kk + tig]);
                a[mi][1] = f2tf32(As_[(m + 8) * 36 + kk + tig]);
                a[mi][2] = f2tf32(As_[m       * 36 + kk + tig + 4]);
                a[mi][3] = f2tf32(As_[(m + 8) * 36 + kk + tig + 4]);
            }
            #pragma unroll
            for (int ni = 0; ni < 4; ++ni) {
                const int n = warp_n * 32 + ni * 8 + grp;
                b[ni][0] = f2tf32(Bs_[(kk + tig)     * 136 + n]);
                b[ni][1] = f2tf32(Bs_[(kk + tig + 4) * 136 + n]);
            }
            #pragma unroll
            for (int mi = 0; mi < 4; ++mi)
                #pragma unroll
                for (int ni = 0; ni < 4; ++ni)
                    mma_tf32(c[mi][ni], a[mi], b[ni]);
        }
        __syncthreads();
    }

    // Epilogue: c0/c1 -> (row, 2*tig / +1); c2/c3 -> row+8. float2 stores.
    #pragma unroll
    for (int ni = 0; ni < 4; ++ni) {
        const int col = bn + warp_n * 32 + ni * 8 + 2 * tig;
        const float bx = __ldg(bias + col);
        const float by = __ldg(bias + col + 1);
        #pragma unroll
        for (int mi = 0; mi < 4; ++mi) {
            const int row0 = bm + warp_m * 64 + mi * 16 + grp;
            float2 v0, v1;
            v0.x = c[mi][ni][0] + bx; v0.y = c[mi][ni][1] + by;
            v1.x = c[mi][ni][2] + bx; v1.y = c[mi][ni][3] + by;
            *reinterpret_cast<float2*>(Cout + (long)row0 * N + col)       = v0;
            *reinterpret_cast<float2*>(Cout + (long)(row0 + 8) * N + col) = v1;
        }
    }
}

// ---------------------------------------------------------------------------
// Small-N SGEMM (FFMA):  C[M,N] = A[M,K] @ B[K,N] + bias[N]
// M % 64 == 0, K % 16 == 0, N arbitrary (column-guarded). 64x64 tile.
// ---------------------------------------------------------------------------
__global__ __launch_bounds__(256) void sgemm_bias_kernel(
    const float* __restrict__ A, const float* __restrict__ Bm,
    const float* __restrict__ bias, float* __restrict__ Cout,
    int M, int N, int K)
{
    __shared__ float As[16][64];   // [k][m]
    __shared__ float Bs[16][64];   // [k][n]

    const int bm = blockIdx.x * 64;
    const int bn = blockIdx.y * 64;
    const int tid = threadIdx.x;
    const int tx = tid & 15;
    const int ty = tid >> 4;

    const int arow = tid >> 2;
    const int ak   = (tid & 3) * 4;
    const int bk   = tid >> 4;
    const int bcol = (tid & 15) * 4;

    float acc[4][4] = {};

    for (int k0 = 0; k0 < K; k0 += 16) {
        float4 a = __ldg(reinterpret_cast<const float4*>(
            A + (long)(bm + arow) * K + k0 + ak));
        As[ak + 0][arow] = a.x;
        As[ak + 1][arow] = a.y;
        As[ak + 2][arow] = a.z;
        As[ak + 3][arow] = a.w;

        const int gk = k0 + bk;
        const int gc = bn + bcol;
        float4 bv;
        bv.x = (gc + 0 < N) ? __ldg(Bm + (long)gk * N + gc + 0) : 0.0f;
        bv.y = (gc + 1 < N) ? __ldg(Bm + (long)gk * N + gc + 1) : 0.0f;
        bv.z = (gc + 2 < N) ? __ldg(Bm + (long)gk * N + gc + 2) : 0.0f;
        bv.w = (gc + 3 < N) ? __ldg(Bm + (long)gk * N + gc + 3) : 0.0f;
        *reinterpret_cast<float4*>(&Bs[bk][bcol]) = bv;

        __syncthreads();

        #pragma unroll
        for (int k = 0; k < 16; ++k) {
            float4 av = *reinterpret_cast<const float4*>(&As[k][ty * 4]);
            float4 bb = *reinterpret_cast<const float4*>(&Bs[k][tx * 4]);
            acc[0][0] += av.x * bb.x; acc[0][1] += av.x * bb.y;
            acc[0][2] += av.x * bb.z; acc[0][3] += av.x * bb.w;
            acc[1][0] += av.y * bb.x; acc[1][1] += av.y * bb.y;
            acc[1][2] += av.y * bb.z; acc[1][3] += av.y * bb.w;
            acc[2][0] += av.z * bb.x; acc[2][1] += av.z * bb.y;
            acc[2][2] += av.z * bb.z; acc[2][3] += av.z * bb.w;
            acc[3][0] += av.w * bb.x; acc[3][1] += av.w * bb.y;
            acc[3][2] += av.w * bb.z; acc[3][3] += av.w * bb.w;
        }
        __syncthreads();
    }

    #pragma unroll
    for (int i = 0; i < 4; ++i) {
        const int row = bm + ty * 4 + i;
        #pragma unroll
        for (int j = 0; j < 4; ++j) {
            const int col = bn + tx * 4 + j;
            if (col < N)
                Cout[(long)row * N + col] = acc[i][j] + __ldg(bias + col);
        }
    }
}

// ---------------------------------------------------------------------------
// Deformable sampling (float2): one block of 128 threads per (b, q).
// Half-warp (16 lanes) per head; each thread handles 2 channels via LDG.64.
// Corner gather per half-warp = one 128B line. Total FFMA unchanged vs v1,
// LDG + address-ALU instruction count halved.
// ---------------------------------------------------------------------------
__global__ __launch_bounds__(128) void deform_sample_kernel(
    const float* __restrict__ ref)
{
    const int row = blockIdx.x;           // b*NQ + q
    const int b   = row / NQ;
    const int h   = threadIdx.x >> 4;     // head (0..7)
    const int sub = threadIdx.x & 15;     // channel pair within head

    const float rx = __ldg(ref + (long)row * 2 + 0);
    const float ry = __ldg(ref + (long)row * 2 + 1);

    const float* qrow = g_qp + (long)row * NQP;
    const float* offp = qrow + h * (NPt * 2);       // offsets at [0,64)
    const float* logp = qrow + 64 + h * NPt;        // attn logits at [64,96)

    // softmax over NP=4 (redundant per 16 lanes; trivial)
    float l0 = logp[0], l1 = logp[1], l2 = logp[2], l3 = logp[3];
    float mx = fmaxf(fmaxf(l0, l1), fmaxf(l2, l3));
    float e[4];
    e[0] = expf(l0 - mx); e[1] = expf(l1 - mx);
    e[2] = expf(l2 - mx); e[3] = expf(l3 - mx);
    const float inv = 1.0f / (e[0] + e[1] + e[2] + e[3]);

    // base pointer for this thread's channel pair (8B aligned)
    const float2* vb = reinterpret_cast<const float2*>(
        g_vp + (long)b * HWp * Cc + h * HDm) + sub;

    float accx = 0.0f, accy = 0.0f;
    #pragma unroll
    for (int p = 0; p < NPt; ++p) {
        const float ox = offp[p * 2 + 0] * (0.1f / (float)Ww);
        const float oy = offp[p * 2 + 1] * (0.1f / (float)Hh);
        const float lx = fminf(fmaxf(rx + ox, 0.0f), 1.0f);
        const float ly = fminf(fmaxf(ry + oy, 0.0f), 1.0f);
        const float gx = fminf(fmaxf(lx * (float)Ww - 0.5f, 0.0f), (float)(Ww - 1));
        const float gy = fminf(fmaxf(ly * (float)Hh - 0.5f, 0.0f), (float)(Hh - 1));
        const float x0f = floorf(gx), y0f = floorf(gy);
        const float fx = gx - x0f, fy = gy - y0f;
        const int x0 = (int)x0f, y0 = (int)y0f;
        const int x1 = min(x0 + 1, Ww - 1);
        const int y1 = min(y0 + 1, Hh - 1);

        const float aw = e[p] * inv;
        const int stride2 = Cc / 2;   // float2 stride per position = 128

        const float2 v00 = __ldg(vb + (long)(y0 * Ww + x0) * stride2);
        const float2 v10 = __ldg(vb + (long)(y0 * Ww + x1) * stride2);
        const float2 v01 = __ldg(vb + (long)(y1 * Ww + x0) * stride2);
        const float2 v11 = __ldg(vb + (long)(y1 * Ww + x1) * stride2);

        const float tx_ = v00.x + fx * (v10.x - v00.x);
        const float bx_ = v01.x + fx * (v11.x - v01.x);
        accx = fmaf(aw, tx_ + fy * (bx_ - tx_), accx);
        const float ty_ = v00.y + fx * (v10.y - v00.y);
        const float by_ = v01.y + fx * (v11.y - v01.y);
        accy = fmaf(aw, ty_ + fy * (by_ - ty_), accy);
    }

    float2 o; o.x = accx; o.y = accy;
    *reinterpret_cast<float2*>(g_mid + (long)row * Cc + h * HDm + sub * 2) = o;
}

// ---------------------------------------------------------------------------
extern "C" void kernel_launch(void* const* d_in, const int* in_sizes, int n_in,
                              void* d_out, int out_size)
{
    const float* query  = (const float*)d_in[0];
    const float* refp   = (const float*)d_in[1];
    const float* value  = (const float*)d_in[2];
    const float* W_off  = (const float*)d_in[3];
    const float* b_off  = (const float*)d_in[4];
    const float* W_attn = (const float*)d_in[5];
    const float* b_attn = (const float*)d_in[6];
    const float* W_val  = (const float*)d_in[7];
    const float* b_val  = (const float*)d_in[8];
    const float* W_out  = (const float*)d_in[9];
    const float* b_out  = (const float*)d_in[10];
    float* out = (float*)d_out;

    // One-time host-side setup (no device allocations).
    static float *vp = nullptr, *qp = nullptr, *mid = nullptr, *Wqp = nullptr, *bqp = nullptr;
    static cudaStream_t s2 = nullptr;
    static cudaEvent_t evFork = nullptr, evJoin = nullptr;
    if (!vp) {
        cudaGetSymbolAddress((void**)&vp,  g_vp);
        cudaGetSymbolAddress((void**)&qp,  g_qp);
        cudaGetSymbolAddress((void**)&mid, g_mid);
        cudaGetSymbolAddress((void**)&Wqp, g_Wqp);
        cudaGetSymbolAddress((void**)&bqp, g_bqp);
        cudaFuncSetAttribute(sgemm_tf32_bias_kernel,
                             cudaFuncAttributeMaxDynamicSharedMemorySize,
                             TF_SMEM_BYTES);
        cudaStreamCreateWithFlags(&s2, cudaStreamNonBlocking);
        cudaEventCreateWithFlags(&evFork, cudaEventDisableTiming);
        cudaEventCreateWithFlags(&evJoin, cudaEventDisableTiming);
    }

    const int Mq = Bb * NQ;     // 32768
    const int Mv = Bb * HWp;    // 65536

    // Fork: value projection runs on s2 concurrently with pack + query-proj.
    cudaEventRecord(evFork, 0);
    cudaStreamWaitEvent(s2, evFork, 0);
    {
        dim3 grid(Mv / 128, Cc / 128);
        sgemm_tf32_bias_kernel<<<grid, 256, TF_SMEM_BYTES, s2>>>(
            value, W_val, b_val, vp, Mv, Cc, Cc);
    }
    cudaEventRecord(evJoin, s2);

    // Main stream: pack weights, then fused query projections.
    pack_qweights_kernel<<<(Cc * NQP + 255) / 256, 256>>>(W_off, b_off, W_attn, b_attn);
    {
        dim3 grid(Mq / 64, (NQP + 63) / 64);
        sgemm_bias_kernel<<<grid, 256>>>(query, Wqp, bqp, qp, Mq, NQP, Cc);
    }

    // Join: sampler needs both vp (s2) and qp (main).
    cudaStreamWaitEvent(0, evJoin, 0);
    deform_sample_kernel<<<Mq, 128>>>(refp);

    // Output projection (tf32 MMA): out = mid @ W_out + b_out   [32768 x 256]
    {
        dim3 grid(Mq / 128, Cc / 128);
        sgemm_tf32_bias_kernel<<<grid, 256, TF_SMEM_BYTES>>>(mid, W_out, b_out, out, Mq, Cc, Cc);
    }
}